// round 6
// baseline (speedup 1.0000x reference)
#include <cuda_runtime.h>
#include <cuda_fp16.h>
#include <float.h>

// Problem constants
#define NWIN   4096
#define NTOK   49
#define CDIM   384
#define HEADS  12
#define HDIM   32
#define MROWS  (NWIN * NTOK)        // 200704
#define QKVCOL (3 * CDIM)           // 1152

// Scratch (allocation-free rule: __device__ globals)
__device__ __half g_xh   [(size_t)MROWS * CDIM];
__device__ __half g_wqkvh[(size_t)CDIM * QKVCOL];
__device__ __half g_wprojh[(size_t)CDIM * CDIM];
__device__ __half g_qkvh [(size_t)MROWS * QKVCOL];
__device__ __half g_atth [(size_t)MROWS * CDIM];

// ---------------------------------------------------------------------------
__global__ void f32_to_f16(const float* __restrict__ in, __half* __restrict__ out, int n4)
{
    int i = blockIdx.x * blockDim.x + threadIdx.x;
    if (i < n4) {
        float4 v = ((const float4*)in)[i];
        ((__half2*)out)[2 * i]     = __floats2half2_rn(v.x, v.y);
        ((__half2*)out)[2 * i + 1] = __floats2half2_rn(v.z, v.w);
    }
}

// ---------------------------------------------------------------------------
// FP16 tensor-core GEMM, 3-stage cp.async pipeline, 1 sync per tile.
// ---------------------------------------------------------------------------
#define BM 128
#define BN 128
#define BKH 32
#define SA 40    // A row stride (80B: conflict-free ldmatrix)
#define SB 136   // B row stride (272B: conflict-free ldmatrix)

__device__ __forceinline__ void ldsm_x4(unsigned& r0, unsigned& r1, unsigned& r2, unsigned& r3,
                                        const void* p) {
    unsigned a = (unsigned)__cvta_generic_to_shared(p);
    asm volatile("ldmatrix.sync.aligned.m8n8.x4.shared.b16 {%0,%1,%2,%3}, [%4];"
                 : "=r"(r0), "=r"(r1), "=r"(r2), "=r"(r3) : "r"(a));
}
__device__ __forceinline__ void ldsm_x4_t(unsigned& r0, unsigned& r1, unsigned& r2, unsigned& r3,
                                          const void* p) {
    unsigned a = (unsigned)__cvta_generic_to_shared(p);
    asm volatile("ldmatrix.sync.aligned.m8n8.x4.trans.shared.b16 {%0,%1,%2,%3}, [%4];"
                 : "=r"(r0), "=r"(r1), "=r"(r2), "=r"(r3) : "r"(a));
}
__device__ __forceinline__ void cp16(const void* smem_dst, const void* gmem_src) {
    unsigned d = (unsigned)__cvta_generic_to_shared(smem_dst);
    asm volatile("cp.async.cg.shared.global [%0], [%1], 16;" :: "r"(d), "l"(gmem_src));
}

template<bool OUT_HALF>
__global__ __launch_bounds__(256) void gemm_f16(
    const __half* __restrict__ A, const __half* __restrict__ B,
    const float* __restrict__ bias, void* __restrict__ Cout,
    int M, int N, int K)
{
    __shared__ __align__(16) __half As[3][BM][SA];
    __shared__ __align__(16) __half Bs[3][BKH][SB];

    const int tid  = threadIdx.x;
    const int lane = tid & 31;
    const int warp = tid >> 5;
    const int warpM = warp & 3;
    const int warpN = warp >> 2;
    const int g = lane >> 2;
    const int c = lane & 3;
    const int blockM = blockIdx.y * BM;
    const int blockN = blockIdx.x * BN;

    const int aRow  = tid >> 2;
    const int aCol8 = (tid & 3) * 8;
    const int bRow  = tid >> 4;
    const int bCol8 = (tid & 15) * 8;

    const __half* Aptr0 = A + (long long)(blockM + aRow) * K + aCol8;
    const __half* Aptr1 = A + (long long)(blockM + aRow + 64) * K + aCol8;
    const __half* Bptr0 = B + (long long)bRow * N + blockN + bCol8;
    const __half* Bptr1 = B + (long long)(bRow + 16) * N + blockN + bCol8;

    float acc[2][8][4];
#pragma unroll
    for (int mt = 0; mt < 2; mt++)
#pragma unroll
        for (int nt = 0; nt < 8; nt++)
#pragma unroll
            for (int r = 0; r < 4; r++) acc[mt][nt][r] = 0.0f;

    const int nTiles = K / BKH;  // 12

#define ISSUE_STAGE(bufi, kt)                                                      \
    do {                                                                           \
        cp16(&As[bufi][aRow][aCol8],      Aptr0 + (kt) * BKH);                     \
        cp16(&As[bufi][aRow + 64][aCol8], Aptr1 + (kt) * BKH);                     \
        cp16(&Bs[bufi][bRow][bCol8],      Bptr0 + (long long)(kt) * BKH * N);      \
        cp16(&Bs[bufi][bRow + 16][bCol8], Bptr1 + (long long)(kt) * BKH * N);      \
    } while (0)

    ISSUE_STAGE(0, 0);
    asm volatile("cp.async.commit_group;");
    ISSUE_STAGE(1, 1);
    asm volatile("cp.async.commit_group;");

    int buf = 0;
    for (int kt = 0; kt < nTiles; kt++) {
        asm volatile("cp.async.wait_group 1;");  // group kt complete
        __syncthreads();
        // Load stage kt+2 into the buffer freed by iteration kt-1 (commit EVERY iter).
        if (kt + 2 < nTiles) {
            int nb = buf + 2; if (nb >= 3) nb -= 3;
            ISSUE_STAGE(nb, kt + 2);
        }
        asm volatile("cp.async.commit_group;");

#pragma unroll
        for (int ks = 0; ks < 2; ks++) {
            const int k0 = ks * 16;
            unsigned af[2][4];
#pragma unroll
            for (int mt = 0; mt < 2; mt++) {
                const int r  = warpM * 32 + mt * 16 + (lane & 15);
                const int cc = k0 + (lane >> 4) * 8;
                ldsm_x4(af[mt][0], af[mt][1], af[mt][2], af[mt][3], &As[buf][r][cc]);
            }
            unsigned bf[4][4];
#pragma unroll
            for (int nb2 = 0; nb2 < 4; nb2++) {
                const int rr = k0 + (lane & 15);
                const int cc = warpN * 64 + nb2 * 16 + (lane >> 4) * 8;
                ldsm_x4_t(bf[nb2][0], bf[nb2][1], bf[nb2][2], bf[nb2][3], &Bs[buf][rr][cc]);
            }
#pragma unroll
            for (int mt = 0; mt < 2; mt++)
#pragma unroll
                for (int nt = 0; nt < 8; nt++) {
                    float* d = acc[mt][nt];
                    const unsigned b0 = bf[nt >> 1][(nt & 1) * 2];
                    const unsigned b1 = bf[nt >> 1][(nt & 1) * 2 + 1];
                    asm volatile(
                        "mma.sync.aligned.m16n8k16.row.col.f32.f16.f16.f32 "
                        "{%0,%1,%2,%3}, {%4,%5,%6,%7}, {%8,%9}, {%0,%1,%2,%3};\n"
                        : "+f"(d[0]), "+f"(d[1]), "+f"(d[2]), "+f"(d[3])
                        : "r"(af[mt][0]), "r"(af[mt][1]), "r"(af[mt][2]), "r"(af[mt][3]),
                          "r"(b0), "r"(b1));
                }
        }
        buf++; if (buf >= 3) buf = 0;
    }

#pragma unroll
    for (int nt = 0; nt < 8; nt++) {
        const int col = blockN + warpN * 64 + nt * 8 + 2 * c;
        const float bv0 = bias[col];
        const float bv1 = bias[col + 1];
#pragma unroll
        for (int mt = 0; mt < 2; mt++) {
            const long long row0 = blockM + warpM * 32 + mt * 16 + g;
            const float c00 = acc[mt][nt][0] + bv0;
            const float c01 = acc[mt][nt][1] + bv1;
            const float c10 = acc[mt][nt][2] + bv0;
            const float c11 = acc[mt][nt][3] + bv1;
            if (OUT_HALF) {
                __half* C = (__half*)Cout;
                *(__half2*)&C[row0 * N + col]       = __floats2half2_rn(c00, c01);
                *(__half2*)&C[(row0 + 8) * N + col] = __floats2half2_rn(c10, c11);
            } else {
                float* C = (float*)Cout;
                float2 v0 = { c00, c01 };
                float2 v1 = { c10, c11 };
                *(float2*)&C[row0 * N + col]       = v0;
                *(float2*)&C[(row0 + 8) * N + col] = v1;
            }
        }
    }
}

// ---------------------------------------------------------------------------
// Window attention v2: block = (window, head), 128 threads (4 warps).
// K columns held in registers (loaded once from gmem), V column in registers
// for PV (lane = d since HDIM == 32). Minimal LDS: broadcasts only.
// ---------------------------------------------------------------------------
__global__ __launch_bounds__(128) void attn_kernel(
    const __half* __restrict__ qkv,
    const float* __restrict__ bias_table,
    __half* __restrict__ out)
{
    __shared__ float qs[NTOK][HDIM + 1];
    __shared__ float vs[NTOK][HDIM + 1];
    __shared__ float P[NTOK][NTOK + 1];
    __shared__ float bt[169];

    const int b    = blockIdx.x;
    const int h    = blockIdx.y;
    const int tid  = threadIdx.x;
    const int lane = tid & 31;
    const int warp = tid >> 5;
    const float scale = 0.17677669529663687f;  // 32^-0.5

    for (int idx = tid; idx < 169; idx += 128) bt[idx] = bias_table[idx * HEADS + h];

    // Stage q (scaled) and v in fp32 smem
    for (int p = tid; p < NTOK * (HDIM / 2); p += 128) {
        const int n = p >> 4;
        const int d = (p & 15) * 2;
        const size_t base = ((size_t)(b * NTOK + n)) * QKVCOL + h * HDIM + d;
        float2 q2 = __half22float2(*(const __half2*)&qkv[base]);
        float2 v2 = __half22float2(*(const __half2*)&qkv[base + 2 * CDIM]);
        qs[n][d] = q2.x * scale;  qs[n][d + 1] = q2.y * scale;
        vs[n][d] = v2.x;          vs[n][d + 1] = v2.y;
    }

    // K columns into registers: lane owns j0 = lane, j1 = lane + 32
    const int j1 = lane + 32;
    const bool v1 = (j1 < NTOK);
    float k0[HDIM], k1[HDIM];
    {
        const __half2* kp0 = (const __half2*)&qkv[((size_t)(b * NTOK + lane)) * QKVCOL + CDIM + h * HDIM];
#pragma unroll
        for (int t = 0; t < 16; t++) {
            float2 f = __half22float2(kp0[t]);
            k0[2 * t] = f.x; k0[2 * t + 1] = f.y;
        }
        if (v1) {
            const __half2* kp1 = (const __half2*)&qkv[((size_t)(b * NTOK + j1)) * QKVCOL + CDIM + h * HDIM];
#pragma unroll
            for (int t = 0; t < 16; t++) {
                float2 f = __half22float2(kp1[t]);
                k1[2 * t] = f.x; k1[2 * t + 1] = f.y;
            }
        } else {
#pragma unroll
            for (int t = 0; t < HDIM; t++) k1[t] = 0.0f;
        }
    }
    __syncthreads();

    // Scores + softmax: warp per row; lane covers columns j0, j1
    const int rj0 = lane / 7, cj0 = lane - rj0 * 7;
    const int rj1 = j1 / 7,   cj1 = j1 - rj1 * 7;
    for (int i = warp; i < NTOK; i += 4) {
        const int ri = i / 7, ci = i - ri * 7;
        float s0 = bt[(ri - rj0 + 6) * 13 + (ci - cj0 + 6)];
        float s1 = v1 ? bt[(ri - rj1 + 6) * 13 + (ci - cj1 + 6)] : 0.0f;
#pragma unroll
        for (int d = 0; d < HDIM; d++) {
            const float qd = qs[i][d];     // smem broadcast
            s0 = fmaf(qd, k0[d], s0);
            s1 = fmaf(qd, k1[d], s1);
        }
        if (!v1) s1 = -FLT_MAX;
        float m = fmaxf(s0, s1);
#pragma unroll
        for (int off = 16; off >= 1; off >>= 1)
            m = fmaxf(m, __shfl_xor_sync(0xffffffffu, m, off));
        const float e0 = __expf(s0 - m);
        const float e1 = v1 ? __expf(s1 - m) : 0.0f;
        float s = e0 + e1;
#pragma unroll
        for (int off = 16; off >= 1; off >>= 1)
            s += __shfl_xor_sync(0xffffffffu, s, off);
        const float inv = 1.0f / s;
        P[i][lane] = e0 * inv;
        if (v1) P[i][j1] = e1 * inv;
    }
    __syncthreads();

    // PV: lane = d, V column in registers, P via smem broadcast. Coalesced fp16 store.
    float vcol[NTOK];
#pragma unroll
    for (int j = 0; j < NTOK; j++) vcol[j] = vs[j][lane];

    for (int i = warp; i < NTOK; i += 4) {
        float o = 0.0f;
#pragma unroll
        for (int j = 0; j < NTOK; j++) o = fmaf(P[i][j], vcol[j], o);
        out[((size_t)(b * NTOK + i)) * CDIM + h * HDIM + lane] = __float2half_rn(o);
    }
}

// ---------------------------------------------------------------------------
extern "C" void kernel_launch(void* const* d_in, const int* in_sizes, int n_in,
                              void* d_out, int out_size)
{
    const float* x          = (const float*)d_in[0];
    const float* w_qkv      = (const float*)d_in[1];
    const float* b_qkv      = (const float*)d_in[2];
    const float* w_proj     = (const float*)d_in[3];
    const float* b_proj     = (const float*)d_in[4];
    const float* bias_table = (const float*)d_in[5];
    float* out = (float*)d_out;

    __half *xh, *wqkvh, *wprojh, *qkvh, *atth;
    cudaGetSymbolAddress((void**)&xh,     g_xh);
    cudaGetSymbolAddress((void**)&wqkvh,  g_wqkvh);
    cudaGetSymbolAddress((void**)&wprojh, g_wprojh);
    cudaGetSymbolAddress((void**)&qkvh,   g_qkvh);
    cudaGetSymbolAddress((void**)&atth,   g_atth);

    // 0) fp32 -> fp16 conversions
    {
        const int n4x = MROWS * CDIM / 4;
        f32_to_f16<<<(n4x + 255) / 256, 256>>>(x, xh, n4x);
        const int n4q = CDIM * QKVCOL / 4;
        f32_to_f16<<<(n4q + 255) / 256, 256>>>(w_qkv, wqkvh, n4q);
        const int n4p = CDIM * CDIM / 4;
        f32_to_f16<<<(n4p + 255) / 256, 256>>>(w_proj, wprojh, n4p);
    }
    // 1) QKV = x @ w_qkv + b_qkv (fp16 out)
    {
        dim3 grid(QKVCOL / BN, MROWS / BM);
        gemm_f16<true><<<grid, 256>>>(xh, wqkvh, b_qkv, qkvh, MROWS, QKVCOL, CDIM);
    }
    // 2) Windowed attention (fp16 in/out)
    {
        dim3 grid(NWIN, HEADS);
        attn_kernel<<<grid, 128>>>(qkvh, bias_table, atth);
    }
    // 3) out = att @ w_proj + b_proj (fp32 out)
    {
        dim3 grid(CDIM / BN, MROWS / BM);
        gemm_f16<false><<<grid, 256>>>(atth, wprojh, b_proj, out, MROWS, CDIM, CDIM);
    }
}

// round 11
// speedup vs baseline: 1.4190x; 1.4190x over previous
#include <cuda_runtime.h>
#include <cuda_fp16.h>
#include <float.h>
#include <string.h>

// Problem constants
#define NWIN   4096
#define NTOK   49
#define CDIM   384
#define HEADS  12
#define HDIM   32
#define MROWS  (NWIN * NTOK)        // 200704
#define QKVCOL (3 * CDIM)           // 1152

// Scratch (allocation-free rule: __device__ globals)
__device__ __half g_xh    [(size_t)MROWS * CDIM];
__device__ __half g_wqkvh [(size_t)CDIM * QKVCOL];
__device__ __half g_wprojh[(size_t)CDIM * CDIM];
__device__ __half g_qkvh  [(size_t)MROWS * QKVCOL];
__device__ __half g_atth  [(size_t)MROWS * CDIM];
__device__ float  g_bias  [HEADS * 64 * 64];       // padded bias, fp32

// ---------------------------------------------------------------------------
__global__ void f32_to_f16(const float* __restrict__ in, __half* __restrict__ out, int n4)
{
    int i = blockIdx.x * blockDim.x + threadIdx.x;
    if (i < n4) {
        float4 v = ((const float4*)in)[i];
        ((__half2*)out)[2 * i]     = __floats2half2_rn(v.x, v.y);
        ((__half2*)out)[2 * i + 1] = __floats2half2_rn(v.z, v.w);
    }
}

// Precompute padded bias: bias_full[h][i][j].
__global__ void build_bias(const float* __restrict__ bias_table, float* __restrict__ bias_full)
{
    int idx = blockIdx.x * blockDim.x + threadIdx.x;   // 12*64*64 = 49152
    if (idx >= HEADS * 64 * 64) return;
    const int h = idx >> 12;
    const int i = (idx >> 6) & 63;
    const int j = idx & 63;
    float v;
    if (i >= NTOK)       v = 0.0f;
    else if (j >= NTOK)  v = -1.0e4f;
    else {
        const int ri = i / 7, ci = i - ri * 7;
        const int rj = j / 7, cj = j - rj * 7;
        const int rel = (ri - rj + 6) * 13 + (ci - cj + 6);
        v = bias_table[rel * HEADS + h];
    }
    bias_full[idx] = v;
}

// ---------------------------------------------------------------------------
// helpers
// ---------------------------------------------------------------------------
__device__ __forceinline__ void ldsm_x4(unsigned& r0, unsigned& r1, unsigned& r2, unsigned& r3,
                                        const void* p) {
    unsigned a = (unsigned)__cvta_generic_to_shared(p);
    asm volatile("ldmatrix.sync.aligned.m8n8.x4.shared.b16 {%0,%1,%2,%3}, [%4];"
                 : "=r"(r0), "=r"(r1), "=r"(r2), "=r"(r3) : "r"(a));
}
__device__ __forceinline__ void ldsm_x4_t(unsigned& r0, unsigned& r1, unsigned& r2, unsigned& r3,
                                          const void* p) {
    unsigned a = (unsigned)__cvta_generic_to_shared(p);
    asm volatile("ldmatrix.sync.aligned.m8n8.x4.trans.shared.b16 {%0,%1,%2,%3}, [%4];"
                 : "=r"(r0), "=r"(r1), "=r"(r2), "=r"(r3) : "r"(a));
}
__device__ __forceinline__ void cp16(const void* smem_dst, const void* gmem_src) {
    unsigned d = (unsigned)__cvta_generic_to_shared(smem_dst);
    asm volatile("cp.async.cg.shared.global [%0], [%1], 16;" :: "r"(d), "l"(gmem_src));
}
__device__ __forceinline__ void mma_f16(float* d, const unsigned* a, unsigned b0, unsigned b1) {
    asm volatile(
        "mma.sync.aligned.m16n8k16.row.col.f32.f16.f16.f32 "
        "{%0,%1,%2,%3}, {%4,%5,%6,%7}, {%8,%9}, {%0,%1,%2,%3};\n"
        : "+f"(d[0]), "+f"(d[1]), "+f"(d[2]), "+f"(d[3])
        : "r"(a[0]), "r"(a[1]), "r"(a[2]), "r"(a[3]), "r"(b0), "r"(b1));
}
// FIX R11: full 32-bit reinterpret of a half2 (R10 used __half2_raw::x = low 16 bits only!)
__device__ __forceinline__ unsigned pack2h(float a, float b) {
    __half2 h = __floats2half2_rn(a, b);
    unsigned u;
    memcpy(&u, &h, 4);
    return u;
}

// ---------------------------------------------------------------------------
// FP16 tensor-core GEMM (3-stage cp.async)
// ---------------------------------------------------------------------------
#define BM 128
#define BN 128
#define BKH 32
#define SA 40
#define SB 136

template<bool OUT_HALF>
__global__ __launch_bounds__(256) void gemm_f16(
    const __half* __restrict__ A, const __half* __restrict__ B,
    const float* __restrict__ bias, void* __restrict__ Cout,
    int M, int N, int K)
{
    __shared__ __align__(16) __half As[3][BM][SA];
    __shared__ __align__(16) __half Bs[3][BKH][SB];

    const int tid  = threadIdx.x;
    const int lane = tid & 31;
    const int warp = tid >> 5;
    const int warpM = warp & 3;
    const int warpN = warp >> 2;
    const int g = lane >> 2;
    const int c = lane & 3;
    const int blockM = blockIdx.y * BM;
    const int blockN = blockIdx.x * BN;

    const int aRow  = tid >> 2;
    const int aCol8 = (tid & 3) * 8;
    const int bRow  = tid >> 4;
    const int bCol8 = (tid & 15) * 8;

    const __half* Aptr0 = A + (long long)(blockM + aRow) * K + aCol8;
    const __half* Aptr1 = A + (long long)(blockM + aRow + 64) * K + aCol8;
    const __half* Bptr0 = B + (long long)bRow * N + blockN + bCol8;
    const __half* Bptr1 = B + (long long)(bRow + 16) * N + blockN + bCol8;

    float acc[2][8][4];
#pragma unroll
    for (int mt = 0; mt < 2; mt++)
#pragma unroll
        for (int nt = 0; nt < 8; nt++)
#pragma unroll
            for (int r = 0; r < 4; r++) acc[mt][nt][r] = 0.0f;

    const int nTiles = K / BKH;

#define ISSUE_STAGE(bufi, kt)                                                      \
    do {                                                                           \
        cp16(&As[bufi][aRow][aCol8],      Aptr0 + (kt) * BKH);                     \
        cp16(&As[bufi][aRow + 64][aCol8], Aptr1 + (kt) * BKH);                     \
        cp16(&Bs[bufi][bRow][bCol8],      Bptr0 + (long long)(kt) * BKH * N);      \
        cp16(&Bs[bufi][bRow + 16][bCol8], Bptr1 + (long long)(kt) * BKH * N);      \
    } while (0)

    ISSUE_STAGE(0, 0);
    asm volatile("cp.async.commit_group;");
    ISSUE_STAGE(1, 1);
    asm volatile("cp.async.commit_group;");

    int buf = 0;
    for (int kt = 0; kt < nTiles; kt++) {
        asm volatile("cp.async.wait_group 1;");
        __syncthreads();
        if (kt + 2 < nTiles) {
            int nb = buf + 2; if (nb >= 3) nb -= 3;
            ISSUE_STAGE(nb, kt + 2);
        }
        asm volatile("cp.async.commit_group;");

#pragma unroll
        for (int ks = 0; ks < 2; ks++) {
            const int k0 = ks * 16;
            unsigned af[2][4];
#pragma unroll
            for (int mt = 0; mt < 2; mt++) {
                const int r  = warpM * 32 + mt * 16 + (lane & 15);
                const int cc = k0 + (lane >> 4) * 8;
                ldsm_x4(af[mt][0], af[mt][1], af[mt][2], af[mt][3], &As[buf][r][cc]);
            }
            unsigned bf[4][4];
#pragma unroll
            for (int nb2 = 0; nb2 < 4; nb2++) {
                const int rr = k0 + (lane & 15);
                const int cc = warpN * 64 + nb2 * 16 + (lane >> 4) * 8;
                ldsm_x4_t(bf[nb2][0], bf[nb2][1], bf[nb2][2], bf[nb2][3], &Bs[buf][rr][cc]);
            }
#pragma unroll
            for (int mt = 0; mt < 2; mt++)
#pragma unroll
                for (int nt = 0; nt < 8; nt++)
                    mma_f16(acc[mt][nt], af[mt],
                            bf[nt >> 1][(nt & 1) * 2], bf[nt >> 1][(nt & 1) * 2 + 1]);
        }
        buf++; if (buf >= 3) buf = 0;
    }

#pragma unroll
    for (int nt = 0; nt < 8; nt++) {
        const int col = blockN + warpN * 64 + nt * 8 + 2 * c;
        const float bv0 = bias[col];
        const float bv1 = bias[col + 1];
#pragma unroll
        for (int mt = 0; mt < 2; mt++) {
            const long long row0 = blockM + warpM * 32 + mt * 16 + g;
            const float c00 = acc[mt][nt][0] + bv0;
            const float c01 = acc[mt][nt][1] + bv1;
            const float c10 = acc[mt][nt][2] + bv0;
            const float c11 = acc[mt][nt][3] + bv1;
            if (OUT_HALF) {
                __half* C = (__half*)Cout;
                *(__half2*)&C[row0 * N + col]       = __floats2half2_rn(c00, c01);
                *(__half2*)&C[(row0 + 8) * N + col] = __floats2half2_rn(c10, c11);
            } else {
                float* C = (float*)Cout;
                float2 v0 = { c00, c01 };
                float2 v1 = { c10, c11 };
                *(float2*)&C[row0 * N + col]       = v0;
                *(float2*)&C[(row0 + 8) * N + col] = v1;
            }
        }
    }
}

// ---------------------------------------------------------------------------
// Tensor-core window attention: warp = (window, head). Block = 2 warps.
// ---------------------------------------------------------------------------
#define AST 40   // smem row stride (halves); 80B => conflict-free ldmatrix

__global__ __launch_bounds__(64) void attn_tc(
    const __half* __restrict__ qkv,
    const float* __restrict__ bias_full,
    __half* __restrict__ out)
{
    __shared__ __align__(16) __half Qs[2][64][AST];
    __shared__ __align__(16) __half Ks[2][64][AST];
    __shared__ __align__(16) __half Vs[2][64][AST];

    const int b    = blockIdx.x;
    const int wrp  = threadIdx.x >> 5;
    const int lane = threadIdx.x & 31;
    const int h    = blockIdx.y * 2 + wrp;
    const int g    = lane >> 2;
    const int c    = lane & 3;
    const float scale = 0.17677669529663687f;  // 32^-0.5
    const __half2 zero2 = __floats2half2_rn(0.f, 0.f);

    // ---- Stage Q (scaled), K, V: 64 rows x 32 halves, zero pad rows ----
    for (int idx = lane; idx < 768; idx += 32) {
        const int t  = idx >> 8;            // 0=Q 1=K 2=V
        const int n  = (idx >> 2) & 63;
        const int ch = idx & 3;
        __half2 v0 = zero2, v1 = zero2, v2 = zero2, v3 = zero2;
        if (n < NTOK) {
            const size_t base = (size_t)(b * NTOK + n) * QKVCOL + t * CDIM + h * HDIM + ch * 8;
            const __half2* p = (const __half2*)&qkv[base];
            v0 = p[0]; v1 = p[1]; v2 = p[2]; v3 = p[3];
            if (t == 0) {
                float2 f;
                f = __half22float2(v0); v0 = __floats2half2_rn(f.x * scale, f.y * scale);
                f = __half22float2(v1); v1 = __floats2half2_rn(f.x * scale, f.y * scale);
                f = __half22float2(v2); v2 = __floats2half2_rn(f.x * scale, f.y * scale);
                f = __half22float2(v3); v3 = __floats2half2_rn(f.x * scale, f.y * scale);
            }
        }
        __half2* dst = (t == 0) ? (__half2*)&Qs[wrp][n][ch * 8]
                     : (t == 1) ? (__half2*)&Ks[wrp][n][ch * 8]
                                : (__half2*)&Vs[wrp][n][ch * 8];
        dst[0] = v0; dst[1] = v1; dst[2] = v2; dst[3] = v3;
    }
    __syncwarp();

    // ---- Init S accumulators with bias fragments ----
    float acc[4][8][4];
    const float* bh = bias_full + h * 4096;
#pragma unroll
    for (int mt = 0; mt < 4; mt++)
#pragma unroll
        for (int nt = 0; nt < 8; nt++) {
            const float2 b0 = *(const float2*)&bh[(16 * mt + g) * 64 + 8 * nt + 2 * c];
            const float2 b1 = *(const float2*)&bh[(16 * mt + 8 + g) * 64 + 8 * nt + 2 * c];
            acc[mt][nt][0] = b0.x; acc[mt][nt][1] = b0.y;
            acc[mt][nt][2] = b1.x; acc[mt][nt][3] = b1.y;
        }

    // ---- S = Q @ K^T ----
#pragma unroll
    for (int kt = 0; kt < 2; kt++) {
        const int k0 = kt * 16;
        unsigned af[4][4];
#pragma unroll
        for (int mt = 0; mt < 4; mt++)
            ldsm_x4(af[mt][0], af[mt][1], af[mt][2], af[mt][3],
                    &Qs[wrp][16 * mt + (lane & 15)][k0 + (lane >> 4) * 8]);
        unsigned bf[4][4];
#pragma unroll
        for (int ntg = 0; ntg < 4; ntg++) {
            const int rr = 16 * ntg + (lane & 7) + ((lane >> 4) & 1) * 8;
            const int cc = k0 + ((lane >> 3) & 1) * 8;
            ldsm_x4(bf[ntg][0], bf[ntg][1], bf[ntg][2], bf[ntg][3], &Ks[wrp][rr][cc]);
        }
#pragma unroll
        for (int mt = 0; mt < 4; mt++)
#pragma unroll
            for (int nt = 0; nt < 8; nt++)
                mma_f16(acc[mt][nt], af[mt],
                        bf[nt >> 1][(nt & 1) * 2], bf[nt >> 1][(nt & 1) * 2 + 1]);
    }

    // ---- Softmax on fragments ----
    float inv[4][2];
#pragma unroll
    for (int mt = 0; mt < 4; mt++) {
#pragma unroll
        for (int rh = 0; rh < 2; rh++) {
            float m = -1e30f;
#pragma unroll
            for (int nt = 0; nt < 8; nt++) {
                m = fmaxf(m, acc[mt][nt][2 * rh]);
                m = fmaxf(m, acc[mt][nt][2 * rh + 1]);
            }
            m = fmaxf(m, __shfl_xor_sync(0xffffffffu, m, 1));
            m = fmaxf(m, __shfl_xor_sync(0xffffffffu, m, 2));
            float s = 0.0f;
#pragma unroll
            for (int nt = 0; nt < 8; nt++) {
                const float e0 = __expf(acc[mt][nt][2 * rh]     - m);
                const float e1 = __expf(acc[mt][nt][2 * rh + 1] - m);
                acc[mt][nt][2 * rh]     = e0;
                acc[mt][nt][2 * rh + 1] = e1;
                s += e0 + e1;
            }
            s += __shfl_xor_sync(0xffffffffu, s, 1);
            s += __shfl_xor_sync(0xffffffffu, s, 2);
            inv[mt][rh] = __fdividef(1.0f, s);
        }
    }

    // ---- Convert P fragments (fp32 acc -> fp16 A-operand) ----
    unsigned pa[4][4][4];
#pragma unroll
    for (int mt = 0; mt < 4; mt++)
#pragma unroll
        for (int kt = 0; kt < 4; kt++) {
            pa[mt][kt][0] = pack2h(acc[mt][2 * kt][0],     acc[mt][2 * kt][1]);
            pa[mt][kt][1] = pack2h(acc[mt][2 * kt][2],     acc[mt][2 * kt][3]);
            pa[mt][kt][2] = pack2h(acc[mt][2 * kt + 1][0], acc[mt][2 * kt + 1][1]);
            pa[mt][kt][3] = pack2h(acc[mt][2 * kt + 1][2], acc[mt][2 * kt + 1][3]);
        }

    // ---- O = P @ V ----
    float oacc[4][4][4];
#pragma unroll
    for (int mt = 0; mt < 4; mt++)
#pragma unroll
        for (int nt = 0; nt < 4; nt++)
#pragma unroll
            for (int r = 0; r < 4; r++) oacc[mt][nt][r] = 0.0f;

#pragma unroll
    for (int kt = 0; kt < 4; kt++) {
        unsigned bv[2][4];
#pragma unroll
        for (int ntg = 0; ntg < 2; ntg++) {
            const int rr = 16 * kt + (lane & 15);
            const int cc = 16 * ntg + (lane >> 4) * 8;
            ldsm_x4_t(bv[ntg][0], bv[ntg][1], bv[ntg][2], bv[ntg][3], &Vs[wrp][rr][cc]);
        }
#pragma unroll
        for (int mt = 0; mt < 4; mt++)
#pragma unroll
            for (int nt = 0; nt < 4; nt++)
                mma_f16(oacc[mt][nt], pa[mt][kt],
                        bv[nt >> 1][(nt & 1) * 2], bv[nt >> 1][(nt & 1) * 2 + 1]);
    }

    // ---- Epilogue: normalize + store fp16 ----
#pragma unroll
    for (int mt = 0; mt < 4; mt++) {
        const int i0 = 16 * mt + g;
        const int i1 = i0 + 8;
#pragma unroll
        for (int nt = 0; nt < 4; nt++) {
            const int col = 8 * nt + 2 * c;
            if (i0 < NTOK) {
                *(__half2*)&out[(size_t)(b * NTOK + i0) * CDIM + h * HDIM + col] =
                    __floats2half2_rn(oacc[mt][nt][0] * inv[mt][0], oacc[mt][nt][1] * inv[mt][0]);
            }
            if (i1 < NTOK) {
                *(__half2*)&out[(size_t)(b * NTOK + i1) * CDIM + h * HDIM + col] =
                    __floats2half2_rn(oacc[mt][nt][2] * inv[mt][1], oacc[mt][nt][3] * inv[mt][1]);
            }
        }
    }
}

// ---------------------------------------------------------------------------
extern "C" void kernel_launch(void* const* d_in, const int* in_sizes, int n_in,
                              void* d_out, int out_size)
{
    const float* x          = (const float*)d_in[0];
    const float* w_qkv      = (const float*)d_in[1];
    const float* b_qkv      = (const float*)d_in[2];
    const float* w_proj     = (const float*)d_in[3];
    const float* b_proj     = (const float*)d_in[4];
    const float* bias_table = (const float*)d_in[5];
    float* out = (float*)d_out;

    __half *xh, *wqkvh, *wprojh, *qkvh, *atth;
    float* biasf;
    cudaGetSymbolAddress((void**)&xh,     g_xh);
    cudaGetSymbolAddress((void**)&wqkvh,  g_wqkvh);
    cudaGetSymbolAddress((void**)&wprojh, g_wprojh);
    cudaGetSymbolAddress((void**)&qkvh,   g_qkvh);
    cudaGetSymbolAddress((void**)&atth,   g_atth);
    cudaGetSymbolAddress((void**)&biasf,  g_bias);

    // 0) conversions + bias build
    {
        const int n4x = MROWS * CDIM / 4;
        f32_to_f16<<<(n4x + 255) / 256, 256>>>(x, xh, n4x);
        const int n4q = CDIM * QKVCOL / 4;
        f32_to_f16<<<(n4q + 255) / 256, 256>>>(w_qkv, wqkvh, n4q);
        const int n4p = CDIM * CDIM / 4;
        f32_to_f16<<<(n4p + 255) / 256, 256>>>(w_proj, wprojh, n4p);
        build_bias<<<(HEADS * 64 * 64 + 1023) / 1024, 1024>>>(bias_table, biasf);
    }
    // 1) QKV = x @ w_qkv + b_qkv (fp16 out)
    {
        dim3 grid(QKVCOL / BN, MROWS / BM);
        gemm_f16<true><<<grid, 256>>>(xh, wqkvh, b_qkv, qkvh, MROWS, QKVCOL, CDIM);
    }
    // 2) Tensor-core windowed attention (fp16 in/out)
    {
        dim3 grid(NWIN, HEADS / 2);
        attn_tc<<<grid, 64>>>(qkvh, biasf, atth);
    }
    // 3) out = att @ w_proj + b_proj (fp32 out)
    {
        dim3 grid(CDIM / BN, MROWS / BM);
        gemm_f16<false><<<grid, 256>>>(atth, wprojh, b_proj, out, MROWS, CDIM, CDIM);
    }
}

// round 13
// speedup vs baseline: 1.8392x; 1.2961x over previous
#include <cuda_runtime.h>
#include <cuda_fp16.h>
#include <float.h>
#include <string.h>

// Problem constants
#define NWIN   4096
#define NTOK   49
#define CDIM   384
#define HEADS  12
#define HDIM   32
#define MROWS  (NWIN * NTOK)        // 200704
#define QKVCOL (3 * CDIM)           // 1152

// Scratch (allocation-free rule: __device__ globals)
__device__ __half g_xh    [(size_t)MROWS * CDIM];
__device__ __half g_wqkvh [(size_t)CDIM * QKVCOL];
__device__ __half g_wprojh[(size_t)CDIM * CDIM];
__device__ __half g_qkvh  [(size_t)MROWS * QKVCOL];
__device__ __half g_atth  [(size_t)MROWS * CDIM];
__device__ float  g_bias  [HEADS * 64 * 64];       // padded bias, fp32

// ---------------------------------------------------------------------------
__global__ void f32_to_f16(const float* __restrict__ in, __half* __restrict__ out, int n4)
{
    int i = blockIdx.x * blockDim.x + threadIdx.x;
    if (i < n4) {
        float4 v = ((const float4*)in)[i];
        ((__half2*)out)[2 * i]     = __floats2half2_rn(v.x, v.y);
        ((__half2*)out)[2 * i + 1] = __floats2half2_rn(v.z, v.w);
    }
}

// Precompute padded bias: bias_full[h][i][j].
__global__ void build_bias(const float* __restrict__ bias_table, float* __restrict__ bias_full)
{
    int idx = blockIdx.x * blockDim.x + threadIdx.x;   // 12*64*64 = 49152
    if (idx >= HEADS * 64 * 64) return;
    const int h = idx >> 12;
    const int i = (idx >> 6) & 63;
    const int j = idx & 63;
    float v;
    if (i >= NTOK)       v = 0.0f;
    else if (j >= NTOK)  v = -1.0e4f;
    else {
        const int ri = i / 7, ci = i - ri * 7;
        const int rj = j / 7, cj = j - rj * 7;
        const int rel = (ri - rj + 6) * 13 + (ci - cj + 6);
        v = bias_table[rel * HEADS + h];
    }
    bias_full[idx] = v;
}

// ---------------------------------------------------------------------------
// helpers
// ---------------------------------------------------------------------------
__device__ __forceinline__ void ldsm_x4(unsigned& r0, unsigned& r1, unsigned& r2, unsigned& r3,
                                        const void* p) {
    unsigned a = (unsigned)__cvta_generic_to_shared(p);
    asm volatile("ldmatrix.sync.aligned.m8n8.x4.shared.b16 {%0,%1,%2,%3}, [%4];"
                 : "=r"(r0), "=r"(r1), "=r"(r2), "=r"(r3) : "r"(a));
}
__device__ __forceinline__ void ldsm_x4_t(unsigned& r0, unsigned& r1, unsigned& r2, unsigned& r3,
                                          const void* p) {
    unsigned a = (unsigned)__cvta_generic_to_shared(p);
    asm volatile("ldmatrix.sync.aligned.m8n8.x4.trans.shared.b16 {%0,%1,%2,%3}, [%4];"
                 : "=r"(r0), "=r"(r1), "=r"(r2), "=r"(r3) : "r"(a));
}
__device__ __forceinline__ void cp16(const void* smem_dst, const void* gmem_src) {
    unsigned d = (unsigned)__cvta_generic_to_shared(smem_dst);
    asm volatile("cp.async.cg.shared.global [%0], [%1], 16;" :: "r"(d), "l"(gmem_src));
}
__device__ __forceinline__ void mma_f16(float* d, const unsigned* a, unsigned b0, unsigned b1) {
    asm volatile(
        "mma.sync.aligned.m16n8k16.row.col.f32.f16.f16.f32 "
        "{%0,%1,%2,%3}, {%4,%5,%6,%7}, {%8,%9}, {%0,%1,%2,%3};\n"
        : "+f"(d[0]), "+f"(d[1]), "+f"(d[2]), "+f"(d[3])
        : "r"(a[0]), "r"(a[1]), "r"(a[2]), "r"(a[3]), "r"(b0), "r"(b1));
}
// Full 32-bit reinterpret of a half2
__device__ __forceinline__ unsigned pack2h(float a, float b) {
    __half2 h = __floats2half2_rn(a, b);
    unsigned u;
    memcpy(&u, &h, 4);
    return u;
}

// ---------------------------------------------------------------------------
// FP16 tensor-core GEMM (3-stage cp.async) — unchanged (validated)
// ---------------------------------------------------------------------------
#define BM 128
#define BN 128
#define BKH 32
#define SA 40
#define SB 136

template<bool OUT_HALF>
__global__ __launch_bounds__(256) void gemm_f16(
    const __half* __restrict__ A, const __half* __restrict__ B,
    const float* __restrict__ bias, void* __restrict__ Cout,
    int M, int N, int K)
{
    __shared__ __align__(16) __half As[3][BM][SA];
    __shared__ __align__(16) __half Bs[3][BKH][SB];

    const int tid  = threadIdx.x;
    const int lane = tid & 31;
    const int warp = tid >> 5;
    const int warpM = warp & 3;
    const int warpN = warp >> 2;
    const int g = lane >> 2;
    const int c = lane & 3;
    const int blockM = blockIdx.y * BM;
    const int blockN = blockIdx.x * BN;

    const int aRow  = tid >> 2;
    const int aCol8 = (tid & 3) * 8;
    const int bRow  = tid >> 4;
    const int bCol8 = (tid & 15) * 8;

    const __half* Aptr0 = A + (long long)(blockM + aRow) * K + aCol8;
    const __half* Aptr1 = A + (long long)(blockM + aRow + 64) * K + aCol8;
    const __half* Bptr0 = B + (long long)bRow * N + blockN + bCol8;
    const __half* Bptr1 = B + (long long)(bRow + 16) * N + blockN + bCol8;

    float acc[2][8][4];
#pragma unroll
    for (int mt = 0; mt < 2; mt++)
#pragma unroll
        for (int nt = 0; nt < 8; nt++)
#pragma unroll
            for (int r = 0; r < 4; r++) acc[mt][nt][r] = 0.0f;

    const int nTiles = K / BKH;

#define ISSUE_STAGE(bufi, kt)                                                      \
    do {                                                                           \
        cp16(&As[bufi][aRow][aCol8],      Aptr0 + (kt) * BKH);                     \
        cp16(&As[bufi][aRow + 64][aCol8], Aptr1 + (kt) * BKH);                     \
        cp16(&Bs[bufi][bRow][bCol8],      Bptr0 + (long long)(kt) * BKH * N);      \
        cp16(&Bs[bufi][bRow + 16][bCol8], Bptr1 + (long long)(kt) * BKH * N);      \
    } while (0)

    ISSUE_STAGE(0, 0);
    asm volatile("cp.async.commit_group;");
    ISSUE_STAGE(1, 1);
    asm volatile("cp.async.commit_group;");

    int buf = 0;
    for (int kt = 0; kt < nTiles; kt++) {
        asm volatile("cp.async.wait_group 1;");
        __syncthreads();
        if (kt + 2 < nTiles) {
            int nb = buf + 2; if (nb >= 3) nb -= 3;
            ISSUE_STAGE(nb, kt + 2);
        }
        asm volatile("cp.async.commit_group;");

#pragma unroll
        for (int ks = 0; ks < 2; ks++) {
            const int k0 = ks * 16;
            unsigned af[2][4];
#pragma unroll
            for (int mt = 0; mt < 2; mt++) {
                const int r  = warpM * 32 + mt * 16 + (lane & 15);
                const int cc = k0 + (lane >> 4) * 8;
                ldsm_x4(af[mt][0], af[mt][1], af[mt][2], af[mt][3], &As[buf][r][cc]);
            }
            unsigned bf[4][4];
#pragma unroll
            for (int nb2 = 0; nb2 < 4; nb2++) {
                const int rr = k0 + (lane & 15);
                const int cc = warpN * 64 + nb2 * 16 + (lane >> 4) * 8;
                ldsm_x4_t(bf[nb2][0], bf[nb2][1], bf[nb2][2], bf[nb2][3], &Bs[buf][rr][cc]);
            }
#pragma unroll
            for (int mt = 0; mt < 2; mt++)
#pragma unroll
                for (int nt = 0; nt < 8; nt++)
                    mma_f16(acc[mt][nt], af[mt],
                            bf[nt >> 1][(nt & 1) * 2], bf[nt >> 1][(nt & 1) * 2 + 1]);
        }
        buf++; if (buf >= 3) buf = 0;
    }

#pragma unroll
    for (int nt = 0; nt < 8; nt++) {
        const int col = blockN + warpN * 64 + nt * 8 + 2 * c;
        const float bv0 = bias[col];
        const float bv1 = bias[col + 1];
#pragma unroll
        for (int mt = 0; mt < 2; mt++) {
            const long long row0 = blockM + warpM * 32 + mt * 16 + g;
            const float c00 = acc[mt][nt][0] + bv0;
            const float c01 = acc[mt][nt][1] + bv1;
            const float c10 = acc[mt][nt][2] + bv0;
            const float c11 = acc[mt][nt][3] + bv1;
            if (OUT_HALF) {
                __half* C = (__half*)Cout;
                *(__half2*)&C[row0 * N + col]       = __floats2half2_rn(c00, c01);
                *(__half2*)&C[(row0 + 8) * N + col] = __floats2half2_rn(c10, c11);
            } else {
                float* C = (float*)Cout;
                float2 v0 = { c00, c01 };
                float2 v1 = { c10, c11 };
                *(float2*)&C[row0 * N + col]       = v0;
                *(float2*)&C[(row0 + 8) * N + col] = v1;
            }
        }
    }
}

// ---------------------------------------------------------------------------
// Tensor-core window attention v2: block = (window, head), 4 warps.
// M=64 rows split across warps (16 rows each); shared Q/K/V smem (one copy).
// Fragment index math identical to validated R11 version with mt -> wrp.
// ---------------------------------------------------------------------------
#define AST 40   // smem row stride (halves); 80B => conflict-free ldmatrix

__global__ __launch_bounds__(128) void attn_tc(
    const __half* __restrict__ qkv,
    const float* __restrict__ bias_full,
    __half* __restrict__ out)
{
    __shared__ __align__(16) __half Qs[64][AST];
    __shared__ __align__(16) __half Ks[64][AST];
    __shared__ __align__(16) __half Vs[64][AST];

    const int b    = blockIdx.x;
    const int h    = blockIdx.y;
    const int tid  = threadIdx.x;
    const int wrp  = tid >> 5;          // warp's m-tile (rows 16*wrp .. 16*wrp+15)
    const int lane = tid & 31;
    const int g    = lane >> 2;
    const int c    = lane & 3;
    const float scale = 0.17677669529663687f;  // 32^-0.5
    const __half2 zero2 = __floats2half2_rn(0.f, 0.f);

    // ---- Stage Q (scaled), K, V: 768 16B-chunks over 128 threads ----
    for (int idx = tid; idx < 768; idx += 128) {
        const int t  = idx >> 8;            // 0=Q 1=K 2=V
        const int n  = (idx >> 2) & 63;
        const int ch = idx & 3;
        __half2 v0 = zero2, v1 = zero2, v2 = zero2, v3 = zero2;
        if (n < NTOK) {
            const size_t base = (size_t)(b * NTOK + n) * QKVCOL + t * CDIM + h * HDIM + ch * 8;
            const __half2* p = (const __half2*)&qkv[base];
            v0 = p[0]; v1 = p[1]; v2 = p[2]; v3 = p[3];
            if (t == 0) {
                float2 f;
                f = __half22float2(v0); v0 = __floats2half2_rn(f.x * scale, f.y * scale);
                f = __half22float2(v1); v1 = __floats2half2_rn(f.x * scale, f.y * scale);
                f = __half22float2(v2); v2 = __floats2half2_rn(f.x * scale, f.y * scale);
                f = __half22float2(v3); v3 = __floats2half2_rn(f.x * scale, f.y * scale);
            }
        }
        __half2* dst = (t == 0) ? (__half2*)&Qs[n][ch * 8]
                     : (t == 1) ? (__half2*)&Ks[n][ch * 8]
                                : (__half2*)&Vs[n][ch * 8];
        dst[0] = v0; dst[1] = v1; dst[2] = v2; dst[3] = v3;
    }
    __syncthreads();

    // ---- Init S accumulators (16 rows x 64 cols per warp) with bias ----
    float acc[8][4];
    const float* bh = bias_full + h * 4096;
#pragma unroll
    for (int nt = 0; nt < 8; nt++) {
        const float2 b0 = *(const float2*)&bh[(16 * wrp + g) * 64 + 8 * nt + 2 * c];
        const float2 b1 = *(const float2*)&bh[(16 * wrp + 8 + g) * 64 + 8 * nt + 2 * c];
        acc[nt][0] = b0.x; acc[nt][1] = b0.y;
        acc[nt][2] = b1.x; acc[nt][3] = b1.y;
    }

    // ---- S = Q @ K^T : 1 m-tile x 8 n-tiles x 2 k16 ----
#pragma unroll
    for (int kt = 0; kt < 2; kt++) {
        const int k0 = kt * 16;
        unsigned af[4];
        ldsm_x4(af[0], af[1], af[2], af[3],
                &Qs[16 * wrp + (lane & 15)][k0 + (lane >> 4) * 8]);
        unsigned bf[4][4];
#pragma unroll
        for (int ntg = 0; ntg < 4; ntg++) {
            const int rr = 16 * ntg + (lane & 7) + ((lane >> 4) & 1) * 8;
            const int cc = k0 + ((lane >> 3) & 1) * 8;
            ldsm_x4(bf[ntg][0], bf[ntg][1], bf[ntg][2], bf[ntg][3], &Ks[rr][cc]);
        }
#pragma unroll
        for (int nt = 0; nt < 8; nt++)
            mma_f16(acc[nt], af,
                    bf[nt >> 1][(nt & 1) * 2], bf[nt >> 1][(nt & 1) * 2 + 1]);
    }

    // ---- Softmax on fragments (rows 16*wrp+g and 16*wrp+8+g) ----
    float inv[2];
#pragma unroll
    for (int rh = 0; rh < 2; rh++) {
        float m = -1e30f;
#pragma unroll
        for (int nt = 0; nt < 8; nt++) {
            m = fmaxf(m, acc[nt][2 * rh]);
            m = fmaxf(m, acc[nt][2 * rh + 1]);
        }
        m = fmaxf(m, __shfl_xor_sync(0xffffffffu, m, 1));
        m = fmaxf(m, __shfl_xor_sync(0xffffffffu, m, 2));
        float s = 0.0f;
#pragma unroll
        for (int nt = 0; nt < 8; nt++) {
            const float e0 = __expf(acc[nt][2 * rh]     - m);
            const float e1 = __expf(acc[nt][2 * rh + 1] - m);
            acc[nt][2 * rh]     = e0;
            acc[nt][2 * rh + 1] = e1;
            s += e0 + e1;
        }
        s += __shfl_xor_sync(0xffffffffu, s, 1);
        s += __shfl_xor_sync(0xffffffffu, s, 2);
        inv[rh] = __fdividef(1.0f, s);
    }

    // ---- Convert P fragments (fp32 acc -> fp16 A-operand), register reuse ----
    unsigned pa[4][4];
#pragma unroll
    for (int kt = 0; kt < 4; kt++) {
        pa[kt][0] = pack2h(acc[2 * kt][0],     acc[2 * kt][1]);
        pa[kt][1] = pack2h(acc[2 * kt][2],     acc[2 * kt][3]);
        pa[kt][2] = pack2h(acc[2 * kt + 1][0], acc[2 * kt + 1][1]);
        pa[kt][3] = pack2h(acc[2 * kt + 1][2], acc[2 * kt + 1][3]);
    }

    // ---- O = P @ V : 1 m-tile x 4 n-tiles x 4 k16 ----
    float oacc[4][4];
#pragma unroll
    for (int nt = 0; nt < 4; nt++)
#pragma unroll
        for (int r = 0; r < 4; r++) oacc[nt][r] = 0.0f;

#pragma unroll
    for (int kt = 0; kt < 4; kt++) {
        unsigned bv[2][4];
#pragma unroll
        for (int ntg = 0; ntg < 2; ntg++) {
            const int rr = 16 * kt + (lane & 15);
            const int cc = 16 * ntg + (lane >> 4) * 8;
            ldsm_x4_t(bv[ntg][0], bv[ntg][1], bv[ntg][2], bv[ntg][3], &Vs[rr][cc]);
        }
#pragma unroll
        for (int nt = 0; nt < 4; nt++)
            mma_f16(oacc[nt], pa[kt],
                    bv[nt >> 1][(nt & 1) * 2], bv[nt >> 1][(nt & 1) * 2 + 1]);
    }

    // ---- Epilogue: normalize + store fp16 ----
    const int i0 = 16 * wrp + g;
    const int i1 = i0 + 8;
#pragma unroll
    for (int nt = 0; nt < 4; nt++) {
        const int col = 8 * nt + 2 * c;
        if (i0 < NTOK) {
            *(__half2*)&out[(size_t)(b * NTOK + i0) * CDIM + h * HDIM + col] =
                __floats2half2_rn(oacc[nt][0] * inv[0], oacc[nt][1] * inv[0]);
        }
        if (i1 < NTOK) {
            *(__half2*)&out[(size_t)(b * NTOK + i1) * CDIM + h * HDIM + col] =
                __floats2half2_rn(oacc[nt][2] * inv[1], oacc[nt][3] * inv[1]);
        }
    }
}

// ---------------------------------------------------------------------------
extern "C" void kernel_launch(void* const* d_in, const int* in_sizes, int n_in,
                              void* d_out, int out_size)
{
    const float* x          = (const float*)d_in[0];
    const float* w_qkv      = (const float*)d_in[1];
    const float* b_qkv      = (const float*)d_in[2];
    const float* w_proj     = (const float*)d_in[3];
    const float* b_proj     = (const float*)d_in[4];
    const float* bias_table = (const float*)d_in[5];
    float* out = (float*)d_out;

    __half *xh, *wqkvh, *wprojh, *qkvh, *atth;
    float* biasf;
    cudaGetSymbolAddress((void**)&xh,     g_xh);
    cudaGetSymbolAddress((void**)&wqkvh,  g_wqkvh);
    cudaGetSymbolAddress((void**)&wprojh, g_wprojh);
    cudaGetSymbolAddress((void**)&qkvh,   g_qkvh);
    cudaGetSymbolAddress((void**)&atth,   g_atth);
    cudaGetSymbolAddress((void**)&biasf,  g_bias);

    // 0) conversions + bias build
    {
        const int n4x = MROWS * CDIM / 4;
        f32_to_f16<<<(n4x + 255) / 256, 256>>>(x, xh, n4x);
        const int n4q = CDIM * QKVCOL / 4;
        f32_to_f16<<<(n4q + 255) / 256, 256>>>(w_qkv, wqkvh, n4q);
        const int n4p = CDIM * CDIM / 4;
        f32_to_f16<<<(n4p + 255) / 256, 256>>>(w_proj, wprojh, n4p);
        build_bias<<<(HEADS * 64 * 64 + 1023) / 1024, 1024>>>(bias_table, biasf);
    }
    // 1) QKV = x @ w_qkv + b_qkv (fp16 out)
    {
        dim3 grid(QKVCOL / BN, MROWS / BM);
        gemm_f16<true><<<grid, 256>>>(xh, wqkvh, b_qkv, qkvh, MROWS, QKVCOL, CDIM);
    }
    // 2) Tensor-core windowed attention (fp16 in/out)
    {
        dim3 grid(NWIN, HEADS);
        attn_tc<<<grid, 128>>>(qkvh, biasf, atth);
    }
    // 3) out = att @ w_proj + b_proj (fp32 out)
    {
        dim3 grid(CDIM / BN, MROWS / BM);
        gemm_f16<false><<<grid, 256>>>(atth, wprojh, b_proj, out, MROWS, CDIM, CDIM);
    }
}